// round 10
// baseline (speedup 1.0000x reference)
#include <cuda_runtime.h>
#include <cuda_fp16.h>
#include <cstdint>

// ---------------------------------------------------------------------------
static constexpr int B_ = 16;
static constexpr int N_ = 2048;
static constexpr int D_ = 64;
static constexpr int NW = N_ / 32;        // 64 mask words per row
// scale/sqrt(2048) * log2(e), folded into Q at convert time; scores then feed
// ex2.approx directly:  exp(q.k/sqrt(N)) == exp2((q*Q2SCALE).k)
#define Q2SCALE_F 0.0318793577f

// Scratch (__device__ globals; no runtime allocation)
__device__ __half    g_Qh[(size_t)B_ * N_ * D_];   // 4 MB  (pre-scaled)
__device__ __half    g_Kh[(size_t)B_ * N_ * D_];   // 4 MB
__device__ __half    g_Vs[(size_t)B_ * N_ * D_];   // 4 MB  V' = V * rd[m]
__device__ unsigned  g_mbN[(size_t)B_ * N_ * NW];  // mask bits, word over m
__device__ unsigned  g_mbT[(size_t)B_ * N_ * NW];  // mask bits, word over n

// ---------------------------------------------------------------------------
__device__ __forceinline__ uint32_t smem_u32(const void* p) {
    uint32_t a;
    asm("{ .reg .u64 t; cvta.to.shared.u64 t, %1; cvt.u32.u64 %0, t; }" : "=r"(a) : "l"(p));
    return a;
}
__device__ __forceinline__ float ex2f(float x) {
    float r; asm("ex2.approx.f32 %0, %1;" : "=f"(r) : "f"(x)); return r;
}
__device__ __forceinline__ void ldsm_x4(uint32_t a[4], uint32_t addr) {
    asm volatile("ldmatrix.sync.aligned.m8n8.x4.shared.b16 {%0,%1,%2,%3}, [%4];"
        : "=r"(a[0]), "=r"(a[1]), "=r"(a[2]), "=r"(a[3]) : "r"(addr));
}
__device__ __forceinline__ void ldsm_x4t(uint32_t a[4], uint32_t addr) {
    asm volatile("ldmatrix.sync.aligned.m8n8.x4.trans.shared.b16 {%0,%1,%2,%3}, [%4];"
        : "=r"(a[0]), "=r"(a[1]), "=r"(a[2]), "=r"(a[3]) : "r"(addr));
}
__device__ __forceinline__ void mma16816(float c[4], const uint32_t a[4], const uint32_t b[2]) {
    asm volatile(
        "mma.sync.aligned.m16n8k16.row.col.f32.f16.f16.f32 "
        "{%0,%1,%2,%3}, {%4,%5,%6,%7}, {%8,%9}, {%0,%1,%2,%3};"
        : "+f"(c[0]), "+f"(c[1]), "+f"(c[2]), "+f"(c[3])
        : "r"(a[0]), "r"(a[1]), "r"(a[2]), "r"(a[3]), "r"(b[0]), "r"(b[1]));
}
__device__ __forceinline__ uint32_t h2u(__half2 h) { return *reinterpret_cast<uint32_t*>(&h); }
__device__ __forceinline__ void cp16(uint32_t dst, const void* src) {
    asm volatile("cp.async.cg.shared.global [%0], [%1], 16;" :: "r"(dst), "l"(src));
}
__device__ __forceinline__ void cp_commit() { asm volatile("cp.async.commit_group;" ::: "memory"); }
__device__ __forceinline__ void cp_wait0()  { asm volatile("cp.async.wait_group 0;"  ::: "memory"); }

// ---------------------------------------------------------------------------
// Prep 1: pack int32 mask into bitmasks in BOTH orientations, one read.
__global__ void pack_mask_kernel(const int* __restrict__ mask) {
    const int warp = blockIdx.x * 8 + (threadIdx.x >> 5);
    const int lane = threadIdx.x & 31;
    const int m_t = warp & 63, n_t = (warp >> 6) & 63, b = warp >> 12;
    const int* src = mask + ((size_t)b * N_ + n_t * 32) * N_ + m_t * 32 + lane;
    unsigned* rowdst = g_mbN + ((size_t)b * N_ + n_t * 32) * NW + m_t;
    unsigned tw = 0;
    #pragma unroll
    for (int i = 0; i < 32; i++) {
        unsigned bal = __ballot_sync(0xffffffffu, src[(size_t)i * N_] != 0);
        if (lane == 0) rowdst[(size_t)i * NW] = bal;
        tw |= ((bal >> lane) & 1u) << i;
    }
    g_mbT[((size_t)b * N_ + m_t * 32 + lane) * NW + n_t] = tw;
}

// Prep 2: q (pre-scaled by SCALE*log2e), k -> fp16
__global__ void convert_qk_kernel(const float* __restrict__ q, const float* __restrict__ k) {
    size_t i = (size_t)blockIdx.x * 256 + threadIdx.x;
    g_Qh[i] = __float2half_rn(q[i] * Q2SCALE_F);
    g_Kh[i] = __float2half_rn(k[i]);
}

// ---------------------------------------------------------------------------
// Colsum: per (b, 64 m-rows): S^T = K·Q^T via HMMA over all n, masked exp2,
// per-lane sums, quad-reduce -> rd; then scale V rows in-block (V' = V*rd).
__global__ void __launch_bounds__(128, 6) colsum_kernel(const float* __restrict__ v) {
    __shared__ __half Kst[64 * 72];
    __shared__ __half Qs[2][64 * 72];
    __shared__ float rdsm[64];
    const int tid = threadIdx.x, w = tid >> 5, lane = tid & 31;
    const int b = blockIdx.y, m0 = blockIdx.x * 64;

    // prefetch Q chunk 0 (async)
    {
        const int4* Qg = (const int4*)(g_Qh + (size_t)b * N_ * D_);
        #pragma unroll 4
        for (int i = tid; i < 512; i += 128) {
            int r = i >> 3, j = i & 7;
            cp16(smem_u32(&Qs[0][r * 72 + j * 8]), Qg + i);
        }
        cp_commit();
    }
    // K tile (plain loads)
    {
        const int4* Kg = (const int4*)(g_Kh + ((size_t)b * N_ + m0) * D_);
        #pragma unroll 4
        for (int i = tid; i < 512; i += 128) {
            int r = i >> 3, j = i & 7;
            *(int4*)&Kst[r * 72 + j * 8] = Kg[i];
        }
    }
    cp_wait0();
    __syncthreads();

    uint32_t Af[4][4];   // A = K rows (m), 4 k16 steps over D=64
    {
        int mat = lane >> 3;
        int row = w * 16 + (mat & 1) * 8 + (lane & 7);
        int colb = (mat >> 1) * 8;
        #pragma unroll
        for (int ks = 0; ks < 4; ks++)
            ldsm_x4(Af[ks], smem_u32(&Kst[row * 72 + ks * 16 + colb]));
    }

    const int mr0 = m0 + w * 16 + (lane >> 2);
    const unsigned* mT0 = g_mbT + ((size_t)b * N_ + mr0) * NW;
    const unsigned* mT1 = mT0 + 8 * NW;
    float acc0 = 0.f, acc1 = 0.f;

    const int r4  = (lane >> 4) * 8 + (lane & 7);       // row within 16-row pair
    const int c4  = ((lane >> 3) & 1) * 8;              // 8-col half select
    const int sh0 = (lane & 3) * 2;

    for (int c = 0; c < 32; c++) {
        if (c + 1 < 32) {   // prefetch next chunk
            const int4* Qg = (const int4*)(g_Qh + ((size_t)b * N_ + (c + 1) * 64) * D_);
            #pragma unroll 4
            for (int i = tid; i < 512; i += 128) {
                int r = i >> 3, j = i & 7;
                cp16(smem_u32(&Qs[(c + 1) & 1][r * 72 + j * 8]), Qg + i);
            }
        }
        cp_commit();

        const __half* Qb = Qs[c & 1];
        // hoisted: pre-shift mask words so per-element tests use constant positions
        const unsigned u0 = mT0[c * 2] >> sh0, u1 = mT0[c * 2 + 1] >> sh0;
        const unsigned v0 = mT1[c * 2] >> sh0, v1 = mT1[c * 2 + 1] >> sh0;

        #pragma unroll
        for (int j2 = 0; j2 < 4; j2++) {
            float c0[4] = {0.f, 0.f, 0.f, 0.f}, c1[4] = {0.f, 0.f, 0.f, 0.f};
            #pragma unroll
            for (int ks = 0; ks < 4; ks++) {
                uint32_t B4[4];
                ldsm_x4(B4, smem_u32(&Qb[(j2 * 16 + r4) * 72 + ks * 16 + c4]));
                mma16816(c0, Af[ks], B4);
                mma16816(c1, Af[ks], B4 + 2);
            }
            const unsigned ua = (j2 < 2) ? u0 : u1;
            const unsigned ub = (j2 < 2) ? v0 : v1;
            const int bb = (j2 & 1) * 16;
            if (!((ua >> bb) & 1))       acc0 += ex2f(c0[0]);
            if (!((ua >> (bb + 1)) & 1)) acc0 += ex2f(c0[1]);
            if (!((ub >> bb) & 1))       acc1 += ex2f(c0[2]);
            if (!((ub >> (bb + 1)) & 1)) acc1 += ex2f(c0[3]);
            if (!((ua >> (bb + 8)) & 1)) acc0 += ex2f(c1[0]);
            if (!((ua >> (bb + 9)) & 1)) acc0 += ex2f(c1[1]);
            if (!((ub >> (bb + 8)) & 1)) acc1 += ex2f(c1[2]);
            if (!((ub >> (bb + 9)) & 1)) acc1 += ex2f(c1[3]);
        }
        cp_wait0();
        __syncthreads();
    }

    acc0 += __shfl_xor_sync(0xffffffffu, acc0, 1);
    acc0 += __shfl_xor_sync(0xffffffffu, acc0, 2);
    acc1 += __shfl_xor_sync(0xffffffffu, acc1, 1);
    acc1 += __shfl_xor_sync(0xffffffffu, acc1, 2);
    if ((lane & 3) == 0) {
        rdsm[w * 16 + (lane >> 2)]     = 1.0f / acc0;
        rdsm[w * 16 + (lane >> 2) + 8] = 1.0f / acc1;
    }
    __syncthreads();

    // Fused: V' = V * rd for this block's 64 m-rows
    {
        const float2* Vg = (const float2*)(v + ((size_t)b * N_ + m0) * D_);
        __half2* Vd = (__half2*)(g_Vs + ((size_t)b * N_ + m0) * D_);
        #pragma unroll 4
        for (int i = tid; i < 64 * 32; i += 128) {
            const float rd = rdsm[i >> 5];
            float2 f = Vg[i];
            Vd[i] = __floats2half2_rn(f.x * rd, f.y * rd);
        }
    }
}

// ---------------------------------------------------------------------------
// Out: per (b, 64 n-rows): loop m chunks of 64 (double-buffered):
//   S = Q·K^T (HMMA) -> masked exp2 -> half2 A-frags -> out += E'·V'
__global__ void __launch_bounds__(128, 4) out_kernel(float* __restrict__ out) {
    extern __shared__ __half dsm[];
    __half* Qst = dsm;                 // 64*72
    __half* Ksb = dsm + 64 * 72;       // 2 x 64*72
    __half* Vsb = Ksb + 2 * 64 * 72;   // 2 x 64*72
    const int tid = threadIdx.x, w = tid >> 5, lane = tid & 31;
    const int b = blockIdx.y, n0 = blockIdx.x * 64;

    // prefetch K/V chunk 0
    {
        const int4* Kg = (const int4*)(g_Kh + (size_t)b * N_ * D_);
        const int4* Vg = (const int4*)(g_Vs + (size_t)b * N_ * D_);
        #pragma unroll 4
        for (int i = tid; i < 512; i += 128) {
            int r = i >> 3, j = i & 7;
            cp16(smem_u32(&Ksb[r * 72 + j * 8]), Kg + i);
            cp16(smem_u32(&Vsb[r * 72 + j * 8]), Vg + i);
        }
        cp_commit();
    }
    // Q tile (plain)
    {
        const int4* Qg = (const int4*)(g_Qh + ((size_t)b * N_ + n0) * D_);
        #pragma unroll 4
        for (int i = tid; i < 512; i += 128) {
            int r = i >> 3, j = i & 7;
            *(int4*)&Qst[r * 72 + j * 8] = Qg[i];
        }
    }
    cp_wait0();
    __syncthreads();

    uint32_t Qa[4][4];
    {
        int mat = lane >> 3;
        int row = w * 16 + (mat & 1) * 8 + (lane & 7);
        int colb = (mat >> 1) * 8;
        #pragma unroll
        for (int ks = 0; ks < 4; ks++)
            ldsm_x4(Qa[ks], smem_u32(&Qst[row * 72 + ks * 16 + colb]));
    }

    float o[8][4];
    #pragma unroll
    for (int dt = 0; dt < 8; dt++)
        #pragma unroll
        for (int e = 0; e < 4; e++) o[dt][e] = 0.f;

    const int nr0 = n0 + w * 16 + (lane >> 2);
    const unsigned* mN0 = g_mbN + ((size_t)b * N_ + nr0) * NW;
    const unsigned* mN1 = mN0 + 8 * NW;

    const int r4  = (lane >> 4) * 8 + (lane & 7);
    const int c4  = ((lane >> 3) & 1) * 8;
    const int sh0 = (lane & 3) * 2;
    const int vr  = lane & 15;
    const int vco = (lane >> 4) * 8;

    for (int c = 0; c < 32; c++) {
        if (c + 1 < 32) {   // prefetch next K/V chunk
            const int4* Kg = (const int4*)(g_Kh + ((size_t)b * N_ + (c + 1) * 64) * D_);
            const int4* Vg = (const int4*)(g_Vs + ((size_t)b * N_ + (c + 1) * 64) * D_);
            const int buf = ((c + 1) & 1) * 64 * 72;
            #pragma unroll 4
            for (int i = tid; i < 512; i += 128) {
                int r = i >> 3, j = i & 7;
                cp16(smem_u32(&Ksb[buf + r * 72 + j * 8]), Kg + i);
                cp16(smem_u32(&Vsb[buf + r * 72 + j * 8]), Vg + i);
            }
        }
        cp_commit();

        const __half* Kb = Ksb + (c & 1) * 64 * 72;
        const __half* Vb = Vsb + (c & 1) * 64 * 72;
        const unsigned u0 = mN0[c * 2] >> sh0, u1 = mN0[c * 2 + 1] >> sh0;
        const unsigned v0 = mN1[c * 2] >> sh0, v1 = mN1[c * 2 + 1] >> sh0;

        #pragma unroll
        for (int j2 = 0; j2 < 4; j2++) {
            float c0[4] = {0.f, 0.f, 0.f, 0.f}, c1[4] = {0.f, 0.f, 0.f, 0.f};
            #pragma unroll
            for (int ks = 0; ks < 4; ks++) {
                uint32_t B4[4];
                ldsm_x4(B4, smem_u32(&Kb[(j2 * 16 + r4) * 72 + ks * 16 + c4]));
                mma16816(c0, Qa[ks], B4);
                mma16816(c1, Qa[ks], B4 + 2);
            }
            const unsigned ua = (j2 < 2) ? u0 : u1;
            const unsigned ub = (j2 < 2) ? v0 : v1;
            const int bb = (j2 & 1) * 16;
            uint32_t Ae[4];
            {   // j = 2*j2 -> k rows 0-7 of A fragment
                float e0 = ((ua >> bb) & 1)       ? 0.f : ex2f(c0[0]);
                float e1 = ((ua >> (bb + 1)) & 1) ? 0.f : ex2f(c0[1]);
                float e2 = ((ub >> bb) & 1)       ? 0.f : ex2f(c0[2]);
                float e3 = ((ub >> (bb + 1)) & 1) ? 0.f : ex2f(c0[3]);
                Ae[0] = h2u(__floats2half2_rn(e0, e1));
                Ae[1] = h2u(__floats2half2_rn(e2, e3));
            }
            {   // j = 2*j2+1 -> k rows 8-15
                float e0 = ((ua >> (bb + 8)) & 1) ? 0.f : ex2f(c1[0]);
                float e1 = ((ua >> (bb + 9)) & 1) ? 0.f : ex2f(c1[1]);
                float e2 = ((ub >> (bb + 8)) & 1) ? 0.f : ex2f(c1[2]);
                float e3 = ((ub >> (bb + 9)) & 1) ? 0.f : ex2f(c1[3]);
                Ae[2] = h2u(__floats2half2_rn(e0, e1));
                Ae[3] = h2u(__floats2half2_rn(e2, e3));
            }
            #pragma unroll
            for (int dt2 = 0; dt2 < 4; dt2++) {
                uint32_t V4[4];
                ldsm_x4t(V4, smem_u32(&Vb[(j2 * 16 + vr) * 72 + dt2 * 16 + vco]));
                mma16816(o[2 * dt2],     Ae, V4);
                mma16816(o[2 * dt2 + 1], Ae, V4 + 2);
            }
        }
        cp_wait0();
        __syncthreads();
    }

    float* obase = out + ((size_t)b * N_ + nr0) * D_;
    const int col0 = (lane & 3) * 2;
    #pragma unroll
    for (int dt = 0; dt < 8; dt++) {
        *(float2*)&obase[dt * 8 + col0]          = make_float2(o[dt][0], o[dt][1]);
        *(float2*)&obase[8 * D_ + dt * 8 + col0] = make_float2(o[dt][2], o[dt][3]);
    }
}

// ---------------------------------------------------------------------------
extern "C" void kernel_launch(void* const* d_in, const int* in_sizes, int n_in,
                              void* d_out, int out_size)
{
    const float* q = (const float*)d_in[0];
    const float* k = (const float*)d_in[1];
    const float* v = (const float*)d_in[2];
    const int* mask = (const int*)d_in[3];
    float* out = (float*)d_out;

    cudaFuncSetAttribute(out_kernel, cudaFuncAttributeMaxDynamicSharedMemorySize, 46080);

    pack_mask_kernel<<<(B_ * 64 * 64) / 8, 256>>>(mask);
    convert_qk_kernel<<<(unsigned)(((size_t)B_ * N_ * D_) / 256), 256>>>(q, k);
    colsum_kernel<<<dim3(N_ / 64, B_), 128>>>(v);
    out_kernel<<<dim3(N_ / 64, B_), 128, 46080>>>(out);
}

// round 11
// speedup vs baseline: 1.6689x; 1.6689x over previous
#include <cuda_runtime.h>
#include <cuda_fp16.h>
#include <cstdint>

// ---------------------------------------------------------------------------
static constexpr int B_ = 16;
static constexpr int N_ = 2048;
static constexpr int D_ = 64;
static constexpr int NW = N_ / 32;        // 64 mask words per row
// 1/sqrt(2048) * log2(e), folded into Q at convert time; scores then feed
// ex2.approx directly:  exp(q.k/sqrt(N)) == exp2((q*Q2SCALE).k)
#define Q2SCALE_F 0.0318793577f

// Scratch (__device__ globals; no runtime allocation)
__device__ __half    g_Qh[(size_t)B_ * N_ * D_];   // 4 MB  (pre-scaled)
__device__ __half    g_Kh[(size_t)B_ * N_ * D_];   // 4 MB
__device__ __half    g_Vs[(size_t)B_ * N_ * D_];   // 4 MB  V' = V * rd[m]
__device__ unsigned  g_mbN[(size_t)B_ * N_ * NW];  // mask bits, word over m
__device__ unsigned  g_mbT[(size_t)B_ * N_ * NW];  // mask bits, word over n

// ---------------------------------------------------------------------------
__device__ __forceinline__ uint32_t smem_u32(const void* p) {
    uint32_t a;
    asm("{ .reg .u64 t; cvta.to.shared.u64 t, %1; cvt.u32.u64 %0, t; }" : "=r"(a) : "l"(p));
    return a;
}
// NOTE: must be called UNCONDITIONALLY (straight-line code). Inline asm cannot
// be speculated by NVVM; putting it under a ternary/if creates divergent
// branches (the R10 regression). Select AFTER the call.
__device__ __forceinline__ float ex2f(float x) {
    float r; asm("ex2.approx.f32 %0, %1;" : "=f"(r) : "f"(x)); return r;
}
__device__ __forceinline__ void ldsm_x4(uint32_t a[4], uint32_t addr) {
    asm volatile("ldmatrix.sync.aligned.m8n8.x4.shared.b16 {%0,%1,%2,%3}, [%4];"
        : "=r"(a[0]), "=r"(a[1]), "=r"(a[2]), "=r"(a[3]) : "r"(addr));
}
__device__ __forceinline__ void ldsm_x4t(uint32_t a[4], uint32_t addr) {
    asm volatile("ldmatrix.sync.aligned.m8n8.x4.trans.shared.b16 {%0,%1,%2,%3}, [%4];"
        : "=r"(a[0]), "=r"(a[1]), "=r"(a[2]), "=r"(a[3]) : "r"(addr));
}
__device__ __forceinline__ void mma16816(float c[4], const uint32_t a[4], const uint32_t b[2]) {
    asm volatile(
        "mma.sync.aligned.m16n8k16.row.col.f32.f16.f16.f32 "
        "{%0,%1,%2,%3}, {%4,%5,%6,%7}, {%8,%9}, {%0,%1,%2,%3};"
        : "+f"(c[0]), "+f"(c[1]), "+f"(c[2]), "+f"(c[3])
        : "r"(a[0]), "r"(a[1]), "r"(a[2]), "r"(a[3]), "r"(b[0]), "r"(b[1]));
}
__device__ __forceinline__ uint32_t h2u(__half2 h) { return *reinterpret_cast<uint32_t*>(&h); }
__device__ __forceinline__ void cp16(uint32_t dst, const void* src) {
    asm volatile("cp.async.cg.shared.global [%0], [%1], 16;" :: "r"(dst), "l"(src));
}
__device__ __forceinline__ void cp_commit() { asm volatile("cp.async.commit_group;" ::: "memory"); }
__device__ __forceinline__ void cp_wait0()  { asm volatile("cp.async.wait_group 0;"  ::: "memory"); }

// ---------------------------------------------------------------------------
// Prep 1: pack int32 mask into bitmasks in BOTH orientations, one read.
__global__ void pack_mask_kernel(const int* __restrict__ mask) {
    const int warp = blockIdx.x * 8 + (threadIdx.x >> 5);
    const int lane = threadIdx.x & 31;
    const int m_t = warp & 63, n_t = (warp >> 6) & 63, b = warp >> 12;
    const int* src = mask + ((size_t)b * N_ + n_t * 32) * N_ + m_t * 32 + lane;
    unsigned* rowdst = g_mbN + ((size_t)b * N_ + n_t * 32) * NW + m_t;
    unsigned tw = 0;
    #pragma unroll
    for (int i = 0; i < 32; i++) {
        unsigned bal = __ballot_sync(0xffffffffu, src[(size_t)i * N_] != 0);
        if (lane == 0) rowdst[(size_t)i * NW] = bal;
        tw |= ((bal >> lane) & 1u) << i;
    }
    g_mbT[((size_t)b * N_ + m_t * 32 + lane) * NW + n_t] = tw;
}

// Prep 2: q (pre-scaled by SCALE*log2e), k -> fp16
__global__ void convert_qk_kernel(const float* __restrict__ q, const float* __restrict__ k) {
    size_t i = (size_t)blockIdx.x * 256 + threadIdx.x;
    g_Qh[i] = __float2half_rn(q[i] * Q2SCALE_F);
    g_Kh[i] = __float2half_rn(k[i]);
}

// ---------------------------------------------------------------------------
// Colsum: per (b, 64 m-rows): S^T = K·Q^T via HMMA over all n, masked exp2,
// per-lane sums, quad-reduce -> rd; then scale V rows in-block (V' = V*rd).
__global__ void __launch_bounds__(128, 4) colsum_kernel(const float* __restrict__ v) {
    __shared__ __half Kst[64 * 72];
    __shared__ __half Qs[2][64 * 72];
    __shared__ float rdsm[64];
    const int tid = threadIdx.x, w = tid >> 5, lane = tid & 31;
    const int b = blockIdx.y, m0 = blockIdx.x * 64;

    // prefetch Q chunk 0 (async)
    {
        const int4* Qg = (const int4*)(g_Qh + (size_t)b * N_ * D_);
        #pragma unroll 4
        for (int i = tid; i < 512; i += 128) {
            int r = i >> 3, j = i & 7;
            cp16(smem_u32(&Qs[0][r * 72 + j * 8]), Qg + i);
        }
        cp_commit();
    }
    // K tile (plain loads)
    {
        const int4* Kg = (const int4*)(g_Kh + ((size_t)b * N_ + m0) * D_);
        #pragma unroll 4
        for (int i = tid; i < 512; i += 128) {
            int r = i >> 3, j = i & 7;
            *(int4*)&Kst[r * 72 + j * 8] = Kg[i];
        }
    }
    cp_wait0();
    __syncthreads();

    uint32_t Af[4][4];   // A = K rows (m), 4 k16 steps over D=64
    {
        int mat = lane >> 3;
        int row = w * 16 + (mat & 1) * 8 + (lane & 7);
        int colb = (mat >> 1) * 8;
        #pragma unroll
        for (int ks = 0; ks < 4; ks++)
            ldsm_x4(Af[ks], smem_u32(&Kst[row * 72 + ks * 16 + colb]));
    }

    const int mr0 = m0 + w * 16 + (lane >> 2);
    const unsigned* mT0 = g_mbT + ((size_t)b * N_ + mr0) * NW;
    const unsigned* mT1 = mT0 + 8 * NW;
    float acc0 = 0.f, acc1 = 0.f;

    const int r4  = (lane >> 4) * 8 + (lane & 7);       // row within 16-row pair
    const int c4  = ((lane >> 3) & 1) * 8;              // 8-col half select
    const int sh0 = (lane & 3) * 2;

    for (int c = 0; c < 32; c++) {
        if (c + 1 < 32) {   // prefetch next chunk
            const int4* Qg = (const int4*)(g_Qh + ((size_t)b * N_ + (c + 1) * 64) * D_);
            #pragma unroll 4
            for (int i = tid; i < 512; i += 128) {
                int r = i >> 3, j = i & 7;
                cp16(smem_u32(&Qs[(c + 1) & 1][r * 72 + j * 8]), Qg + i);
            }
        }
        cp_commit();

        const __half* Qb = Qs[c & 1];
        // pre-shifted mask words: per-element tests are constant-position
        const unsigned u0 = mT0[c * 2] >> sh0, u1 = mT0[c * 2 + 1] >> sh0;
        const unsigned v0 = mT1[c * 2] >> sh0, v1 = mT1[c * 2 + 1] >> sh0;

        #pragma unroll
        for (int j2 = 0; j2 < 4; j2++) {
            float c0[4] = {0.f, 0.f, 0.f, 0.f}, c1[4] = {0.f, 0.f, 0.f, 0.f};
            #pragma unroll
            for (int ks = 0; ks < 4; ks++) {
                uint32_t B4[4];
                ldsm_x4(B4, smem_u32(&Qb[(j2 * 16 + r4) * 72 + ks * 16 + c4]));
                mma16816(c0, Af[ks], B4);
                mma16816(c1, Af[ks], B4 + 2);
            }
            const unsigned ua = (j2 < 2) ? u0 : u1;
            const unsigned ub = (j2 < 2) ? v0 : v1;
            const int bb = (j2 & 1) * 16;
            // ex2 computed unconditionally (straight-line asm); predicated adds.
            float e00 = ex2f(c0[0]), e01 = ex2f(c0[1]);
            float e02 = ex2f(c0[2]), e03 = ex2f(c0[3]);
            float e10 = ex2f(c1[0]), e11 = ex2f(c1[1]);
            float e12 = ex2f(c1[2]), e13 = ex2f(c1[3]);
            if (!((ua >> bb) & 1))       acc0 += e00;
            if (!((ua >> (bb + 1)) & 1)) acc0 += e01;
            if (!((ub >> bb) & 1))       acc1 += e02;
            if (!((ub >> (bb + 1)) & 1)) acc1 += e03;
            if (!((ua >> (bb + 8)) & 1)) acc0 += e10;
            if (!((ua >> (bb + 9)) & 1)) acc0 += e11;
            if (!((ub >> (bb + 8)) & 1)) acc1 += e12;
            if (!((ub >> (bb + 9)) & 1)) acc1 += e13;
        }
        cp_wait0();
        __syncthreads();
    }

    acc0 += __shfl_xor_sync(0xffffffffu, acc0, 1);
    acc0 += __shfl_xor_sync(0xffffffffu, acc0, 2);
    acc1 += __shfl_xor_sync(0xffffffffu, acc1, 1);
    acc1 += __shfl_xor_sync(0xffffffffu, acc1, 2);
    if ((lane & 3) == 0) {
        rdsm[w * 16 + (lane >> 2)]     = 1.0f / acc0;
        rdsm[w * 16 + (lane >> 2) + 8] = 1.0f / acc1;
    }
    __syncthreads();

    // Fused: V' = V * rd for this block's 64 m-rows
    {
        const float2* Vg = (const float2*)(v + ((size_t)b * N_ + m0) * D_);
        __half2* Vd = (__half2*)(g_Vs + ((size_t)b * N_ + m0) * D_);
        #pragma unroll 4
        for (int i = tid; i < 64 * 32; i += 128) {
            const float rd = rdsm[i >> 5];
            float2 f = Vg[i];
            Vd[i] = __floats2half2_rn(f.x * rd, f.y * rd);
        }
    }
}

// ---------------------------------------------------------------------------
// Out: per (b, 64 n-rows): loop m chunks of 64 (double-buffered):
//   S = Q·K^T (HMMA) -> masked exp2 -> half2 A-frags -> out += E'·V'
__global__ void __launch_bounds__(128, 4) out_kernel(float* __restrict__ out) {
    extern __shared__ __half dsm[];
    __half* Qst = dsm;                 // 64*72
    __half* Ksb = dsm + 64 * 72;       // 2 x 64*72
    __half* Vsb = Ksb + 2 * 64 * 72;   // 2 x 64*72
    const int tid = threadIdx.x, w = tid >> 5, lane = tid & 31;
    const int b = blockIdx.y, n0 = blockIdx.x * 64;

    // prefetch K/V chunk 0
    {
        const int4* Kg = (const int4*)(g_Kh + (size_t)b * N_ * D_);
        const int4* Vg = (const int4*)(g_Vs + (size_t)b * N_ * D_);
        #pragma unroll 4
        for (int i = tid; i < 512; i += 128) {
            int r = i >> 3, j = i & 7;
            cp16(smem_u32(&Ksb[r * 72 + j * 8]), Kg + i);
            cp16(smem_u32(&Vsb[r * 72 + j * 8]), Vg + i);
        }
        cp_commit();
    }
    // Q tile (plain)
    {
        const int4* Qg = (const int4*)(g_Qh + ((size_t)b * N_ + n0) * D_);
        #pragma unroll 4
        for (int i = tid; i < 512; i += 128) {
            int r = i >> 3, j = i & 7;
            *(int4*)&Qst[r * 72 + j * 8] = Qg[i];
        }
    }
    cp_wait0();
    __syncthreads();

    uint32_t Qa[4][4];
    {
        int mat = lane >> 3;
        int row = w * 16 + (mat & 1) * 8 + (lane & 7);
        int colb = (mat >> 1) * 8;
        #pragma unroll
        for (int ks = 0; ks < 4; ks++)
            ldsm_x4(Qa[ks], smem_u32(&Qst[row * 72 + ks * 16 + colb]));
    }

    float o[8][4];
    #pragma unroll
    for (int dt = 0; dt < 8; dt++)
        #pragma unroll
        for (int e = 0; e < 4; e++) o[dt][e] = 0.f;

    const int nr0 = n0 + w * 16 + (lane >> 2);
    const unsigned* mN0 = g_mbN + ((size_t)b * N_ + nr0) * NW;
    const unsigned* mN1 = mN0 + 8 * NW;

    const int r4  = (lane >> 4) * 8 + (lane & 7);
    const int c4  = ((lane >> 3) & 1) * 8;
    const int sh0 = (lane & 3) * 2;
    const int vr  = lane & 15;
    const int vco = (lane >> 4) * 8;

    for (int c = 0; c < 32; c++) {
        if (c + 1 < 32) {   // prefetch next K/V chunk
            const int4* Kg = (const int4*)(g_Kh + ((size_t)b * N_ + (c + 1) * 64) * D_);
            const int4* Vg = (const int4*)(g_Vs + ((size_t)b * N_ + (c + 1) * 64) * D_);
            const int buf = ((c + 1) & 1) * 64 * 72;
            #pragma unroll 4
            for (int i = tid; i < 512; i += 128) {
                int r = i >> 3, j = i & 7;
                cp16(smem_u32(&Ksb[buf + r * 72 + j * 8]), Kg + i);
                cp16(smem_u32(&Vsb[buf + r * 72 + j * 8]), Vg + i);
            }
        }
        cp_commit();

        const __half* Kb = Ksb + (c & 1) * 64 * 72;
        const __half* Vb = Vsb + (c & 1) * 64 * 72;
        const unsigned u0 = mN0[c * 2] >> sh0, u1 = mN0[c * 2 + 1] >> sh0;
        const unsigned v0 = mN1[c * 2] >> sh0, v1 = mN1[c * 2 + 1] >> sh0;

        #pragma unroll
        for (int j2 = 0; j2 < 4; j2++) {
            float c0[4] = {0.f, 0.f, 0.f, 0.f}, c1[4] = {0.f, 0.f, 0.f, 0.f};
            #pragma unroll
            for (int ks = 0; ks < 4; ks++) {
                uint32_t B4[4];
                ldsm_x4(B4, smem_u32(&Kb[(j2 * 16 + r4) * 72 + ks * 16 + c4]));
                mma16816(c0, Qa[ks], B4);
                mma16816(c1, Qa[ks], B4 + 2);
            }
            const unsigned ua = (j2 < 2) ? u0 : u1;
            const unsigned ub = (j2 < 2) ? v0 : v1;
            const int bb = (j2 & 1) * 16;
            // ex2 unconditionally, then FSEL to zero — no branches around asm.
            float e00 = ex2f(c0[0]), e01 = ex2f(c0[1]);
            float e02 = ex2f(c0[2]), e03 = ex2f(c0[3]);
            float e10 = ex2f(c1[0]), e11 = ex2f(c1[1]);
            float e12 = ex2f(c1[2]), e13 = ex2f(c1[3]);
            if ((ua >> bb) & 1)       e00 = 0.f;
            if ((ua >> (bb + 1)) & 1) e01 = 0.f;
            if ((ub >> bb) & 1)       e02 = 0.f;
            if ((ub >> (bb + 1)) & 1) e03 = 0.f;
            if ((ua >> (bb + 8)) & 1) e10 = 0.f;
            if ((ua >> (bb + 9)) & 1) e11 = 0.f;
            if ((ub >> (bb + 8)) & 1) e12 = 0.f;
            if ((ub >> (bb + 9)) & 1) e13 = 0.f;
            uint32_t Ae[4];
            Ae[0] = h2u(__floats2half2_rn(e00, e01));
            Ae[1] = h2u(__floats2half2_rn(e02, e03));
            Ae[2] = h2u(__floats2half2_rn(e10, e11));
            Ae[3] = h2u(__floats2half2_rn(e12, e13));
            #pragma unroll
            for (int dt2 = 0; dt2 < 4; dt2++) {
                uint32_t V4[4];
                ldsm_x4t(V4, smem_u32(&Vb[(j2 * 16 + vr) * 72 + dt2 * 16 + vco]));
                mma16816(o[2 * dt2],     Ae, V4);
                mma16816(o[2 * dt2 + 1], Ae, V4 + 2);
            }
        }
        cp_wait0();
        __syncthreads();
    }

    float* obase = out + ((size_t)b * N_ + nr0) * D_;
    const int col0 = (lane & 3) * 2;
    #pragma unroll
    for (int dt = 0; dt < 8; dt++) {
        *(float2*)&obase[dt * 8 + col0]          = make_float2(o[dt][0], o[dt][1]);
        *(float2*)&obase[8 * D_ + dt * 8 + col0] = make_float2(o[dt][2], o[dt][3]);
    }
}

// ---------------------------------------------------------------------------
extern "C" void kernel_launch(void* const* d_in, const int* in_sizes, int n_in,
                              void* d_out, int out_size)
{
    const float* q = (const float*)d_in[0];
    const float* k = (const float*)d_in[1];
    const float* v = (const float*)d_in[2];
    const int* mask = (const int*)d_in[3];
    float* out = (float*)d_out;

    cudaFuncSetAttribute(out_kernel, cudaFuncAttributeMaxDynamicSharedMemorySize, 46080);

    pack_mask_kernel<<<(B_ * 64 * 64) / 8, 256>>>(mask);
    convert_qk_kernel<<<(unsigned)(((size_t)B_ * N_ * D_) / 256), 256>>>(q, k);
    colsum_kernel<<<dim3(N_ / 64, B_), 128>>>(v);
    out_kernel<<<dim3(N_ / 64, B_), 128, 46080>>>(out);
}